// round 7
// baseline (speedup 1.0000x reference)
#include <cuda_runtime.h>

#define N 512
#define D 256
#define KSPLIT 8

// Scratch (device globals — no allocation allowed)
__device__ float g_q[N * N];
__device__ float g_k[N * N];
__device__ float g_v[N * N];
__device__ float g_s[N * N];
__device__ float g_sp[KSPLIT][N * N];   // split-K partials of q@k
__device__ float g_op[KSPLIT][N * N];   // split-K partials of s@v

#define PROJ_BLOCKS 1184   // 148 * 8 (persistent single wave)

// ---------------------------------------------------------------------------
// Kernel 1: fused rank-1 projections, persistent grid-stride, warp per row.
// 768 MB streaming reads — HBM-bound at ~6.9 TB/s (near ceiling).
// ---------------------------------------------------------------------------
__global__ void __launch_bounds__(256) proj_kernel(
    const float* __restrict__ xq, const float* __restrict__ xk,
    const float* __restrict__ xv, const float* __restrict__ WQ,
    const float* __restrict__ WK, const float* __restrict__ WV)
{
    __shared__ float sW[3][D];
    int tid = threadIdx.x;
    sW[0][tid] = WQ[tid];
    sW[1][tid] = WK[tid];
    sW[2][tid] = WV[tid];
    __syncthreads();

    const int warp = tid >> 5;
    const int lane = tid & 31;
    const long long stride = (long long)PROJ_BLOCKS * 8;
    const long long total = 3LL * N * N;

    for (long long row = (long long)blockIdx.x * 8 + warp; row < total; row += stride) {
        int t = (int)(row >> 18);
        int r = (int)(row & (N * N - 1));

        const float* x = (t == 0) ? xq : (t == 1) ? xk : xv;
        const float4* xr = reinterpret_cast<const float4*>(x + (size_t)r * D);
        const float4* w4 = reinterpret_cast<const float4*>(sW[t]);

        float4 a0 = __ldcs(&xr[lane]);
        float4 a1 = __ldcs(&xr[lane + 32]);
        float4 b0 = w4[lane];
        float4 b1 = w4[lane + 32];

        float acc = a0.x * b0.x + a0.y * b0.y + a0.z * b0.z + a0.w * b0.w
                  + a1.x * b1.x + a1.y * b1.y + a1.z * b1.z + a1.w * b1.w;

#pragma unroll
        for (int o = 16; o > 0; o >>= 1)
            acc += __shfl_xor_sync(0xffffffffu, acc, o);

        if (lane == 0) {
            float* g = (t == 0) ? g_q : (t == 1) ? g_k : g_v;
            g[r] = acc;
        }
    }
}

// ---------------------------------------------------------------------------
// Kernel 2/4: split-K SGEMM partials. BM=128, BN=64, BK=32; 128 threads;
// 8x8 microtile (64 accumulators -> deep FFMA ILP). grid (8,4,KSPLIT)=256.
// mode 0: g_sp[z] = q@k K-slice;  mode 1: g_op[z] = s@v K-slice.
// ---------------------------------------------------------------------------
__global__ void __launch_bounds__(128, 4) sgemm_kernel(int mode)
{
    const float* __restrict__ A = (mode == 0) ? g_q : g_s;
    const float* __restrict__ B = (mode == 0) ? g_k : g_v;
    float* __restrict__ C = (mode == 0) ? g_sp[blockIdx.z] : g_op[blockIdx.z];

    __shared__ float As[32][136];   // [k][m], pad 8: 16B-aligned rows, bank-spread
    __shared__ float Bs[32][68];    // [k][n], pad 4

    const int bx = blockIdx.x * 64;               // n offset
    const int by = blockIdx.y * 128;              // m offset
    const int kbase = blockIdx.z * (N / KSPLIT);  // 64-wide K slice
    const int tid = threadIdx.x;
    const int tx = tid & 7;                       // n micro (8*8 = 64)
    const int ty = tid >> 3;                      // m micro (16*8 = 128)

    float acc[8][8] = {};

    for (int k0 = 0; k0 < N / KSPLIT; k0 += 32) {
        // --- Fill As: thread = A row m=tid; load 32 k-floats, store transposed
        {
            const float4* src = (const float4*)&A[(by + tid) * N + kbase + k0];
#pragma unroll
            for (int t = 0; t < 8; t++) {
                float4 v = src[t];
                As[t * 4 + 0][tid] = v.x;
                As[t * 4 + 1][tid] = v.y;
                As[t * 4 + 2][tid] = v.z;
                As[t * 4 + 3][tid] = v.w;
            }
        }
        // --- Fill Bs: 2048 floats = 512 float4; 4 per thread
#pragma unroll
        for (int t = 0; t < 4; t++) {
            int c = tid + t * 128;
            int k = c >> 4, j = (c & 15) * 4;
            *(float4*)&Bs[k][j] = *(const float4*)&B[(kbase + k0 + k) * N + bx + j];
        }
        __syncthreads();

#pragma unroll
        for (int kk = 0; kk < 32; kk++) {
            float4 a0 = *(const float4*)&As[kk][ty * 8];
            float4 a1 = *(const float4*)&As[kk][ty * 8 + 4];
            float4 b0 = *(const float4*)&Bs[kk][tx * 8];
            float4 b1 = *(const float4*)&Bs[kk][tx * 8 + 4];
            const float* ap0 = (const float*)&a0;
            const float* ap1 = (const float*)&a1;
            const float* bp0 = (const float*)&b0;
            const float* bp1 = (const float*)&b1;
#pragma unroll
            for (int i = 0; i < 4; i++)
#pragma unroll
                for (int j = 0; j < 4; j++) {
                    acc[i][j]         += ap0[i] * bp0[j];
                    acc[i][j + 4]     += ap0[i] * bp1[j];
                    acc[i + 4][j]     += ap1[i] * bp0[j];
                    acc[i + 4][j + 4] += ap1[i] * bp1[j];
                }
        }
        __syncthreads();
    }

#pragma unroll
    for (int i = 0; i < 8; i++) {
        int row = (by + ty * 8 + i) * N + bx + tx * 8;
        *(float4*)&C[row]     = make_float4(acc[i][0], acc[i][1], acc[i][2], acc[i][3]);
        *(float4*)&C[row + 4] = make_float4(acc[i][4], acc[i][5], acc[i][6], acc[i][7]);
    }
}

// ---------------------------------------------------------------------------
// Kernel 3: sum KSPLIT s-partials + row softmax -> g_s.
// 2 rows per block; 128 threads/row; float4 per thread; shuffle reduce.
// ---------------------------------------------------------------------------
__global__ void __launch_bounds__(256) softmax_kernel()
{
    __shared__ float smax[2][4];
    __shared__ float ssum[2][4];

    const int tid = threadIdx.x;
    const int half = tid >> 7;              // 0 or 1 (which row)
    const int t = tid & 127;
    const int warp = (tid >> 5) & 3;        // warp within the row group
    const int lane = tid & 31;
    const int row = blockIdx.x * 2 + half;
    const size_t off = (size_t)row * N + t * 4;

    float4 a = make_float4(0.f, 0.f, 0.f, 0.f);
#pragma unroll
    for (int z = 0; z < KSPLIT; z++) {
        float4 p = *(const float4*)&g_sp[z][off];
        a.x += p.x; a.y += p.y; a.z += p.z; a.w += p.w;
    }

    float mx = fmaxf(fmaxf(a.x, a.y), fmaxf(a.z, a.w));
#pragma unroll
    for (int o = 16; o > 0; o >>= 1)
        mx = fmaxf(mx, __shfl_xor_sync(0xffffffffu, mx, o));
    if (lane == 0) smax[half][warp] = mx;
    __syncthreads();
    mx = fmaxf(fmaxf(smax[half][0], smax[half][1]),
               fmaxf(smax[half][2], smax[half][3]));

    float4 e;
    e.x = __expf(a.x - mx);
    e.y = __expf(a.y - mx);
    e.z = __expf(a.z - mx);
    e.w = __expf(a.w - mx);

    float s = e.x + e.y + e.z + e.w;
#pragma unroll
    for (int o = 16; o > 0; o >>= 1)
        s += __shfl_xor_sync(0xffffffffu, s, o);
    if (lane == 0) ssum[half][warp] = s;
    __syncthreads();
    float inv = 1.0f / (ssum[half][0] + ssum[half][1] + ssum[half][2] + ssum[half][3]);

    e.x *= inv; e.y *= inv; e.z *= inv; e.w *= inv;
    *(float4*)&g_s[off] = e;
}

// ---------------------------------------------------------------------------
// Kernel 5: sum KSPLIT out-partials -> d_out.
// ---------------------------------------------------------------------------
__global__ void __launch_bounds__(256) reduce_out_kernel(float* __restrict__ out)
{
    int i = blockIdx.x * 256 + threadIdx.x;
    float4 r = ((const float4*)g_op[0])[i];
#pragma unroll
    for (int z = 1; z < KSPLIT; z++) {
        float4 s = ((const float4*)g_op[z])[i];
        r.x += s.x; r.y += s.y; r.z += s.z; r.w += s.w;
    }
    ((float4*)out)[i] = r;
}

// ---------------------------------------------------------------------------
extern "C" void kernel_launch(void* const* d_in, const int* in_sizes, int n_in,
                              void* d_out, int out_size)
{
    const float* xq = (const float*)d_in[0];
    const float* xk = (const float*)d_in[1];
    const float* xv = (const float*)d_in[2];
    const float* WQ = (const float*)d_in[3];
    const float* WK = (const float*)d_in[4];
    const float* WV = (const float*)d_in[5];
    float* out = (float*)d_out;

    proj_kernel<<<PROJ_BLOCKS, 256>>>(xq, xk, xv, WQ, WK, WV);

    dim3 gg(N / 64, N / 128, KSPLIT);   // (8, 4, 8) = 256 blocks, 128 thr
    sgemm_kernel<<<gg, 128>>>(0);

    softmax_kernel<<<N / 2, 256>>>();

    sgemm_kernel<<<gg, 128>>>(1);

    reduce_out_kernel<<<(N * N / 4) / 256, 256>>>(out);
}

// round 8
// speedup vs baseline: 1.0572x; 1.0572x over previous
#include <cuda_runtime.h>

#define N 512
#define D 256
#define KSPLIT 8

// Scratch (device globals — no allocation allowed)
__device__ float g_q[N * N];
__device__ float g_k[N * N];
__device__ float g_v[N * N];
__device__ float g_s[N * N];
__device__ float g_sp[KSPLIT][N * N];   // split-K partials of q@k
__device__ float g_op[KSPLIT][N * N];   // split-K partials of s@v

#define PROJ_BLOCKS 1184   // 148 * 8 (persistent single wave)

// ---------------------------------------------------------------------------
// Kernel 1: fused rank-1 projections, persistent grid-stride, warp per row.
// 768 MB streaming reads — HBM-bound at ~6.9 TB/s.
// ---------------------------------------------------------------------------
__global__ void __launch_bounds__(256) proj_kernel(
    const float* __restrict__ xq, const float* __restrict__ xk,
    const float* __restrict__ xv, const float* __restrict__ WQ,
    const float* __restrict__ WK, const float* __restrict__ WV)
{
    __shared__ float sW[3][D];
    int tid = threadIdx.x;
    sW[0][tid] = WQ[tid];
    sW[1][tid] = WK[tid];
    sW[2][tid] = WV[tid];
    __syncthreads();

    const int warp = tid >> 5;
    const int lane = tid & 31;
    const long long stride = (long long)PROJ_BLOCKS * 8;
    const long long total = 3LL * N * N;

    for (long long row = (long long)blockIdx.x * 8 + warp; row < total; row += stride) {
        int t = (int)(row >> 18);
        int r = (int)(row & (N * N - 1));

        const float* x = (t == 0) ? xq : (t == 1) ? xk : xv;
        const float4* xr = reinterpret_cast<const float4*>(x + (size_t)r * D);
        const float4* w4 = reinterpret_cast<const float4*>(sW[t]);

        float4 a0 = __ldcs(&xr[lane]);
        float4 a1 = __ldcs(&xr[lane + 32]);
        float4 b0 = w4[lane];
        float4 b1 = w4[lane + 32];

        float acc = a0.x * b0.x + a0.y * b0.y + a0.z * b0.z + a0.w * b0.w
                  + a1.x * b1.x + a1.y * b1.y + a1.z * b1.z + a1.w * b1.w;

#pragma unroll
        for (int o = 16; o > 0; o >>= 1)
            acc += __shfl_xor_sync(0xffffffffu, acc, o);

        if (lane == 0) {
            float* g = (t == 0) ? g_q : (t == 1) ? g_k : g_v;
            g[r] = acc;
        }
    }
}

// ---------------------------------------------------------------------------
// Kernel 2/4: split-K SGEMM partials (R5 config — best measured).
// BM=128, BN=64, BK=32; 256 threads; 8x4 microtile; grid (8,4,KSPLIT)=256.
// mode 0: g_sp[z] = q@k K-slice;  mode 1: g_op[z] = s@v K-slice.
// ---------------------------------------------------------------------------
__global__ void __launch_bounds__(256, 2) sgemm_kernel(int mode)
{
    const float* __restrict__ A = (mode == 0) ? g_q : g_s;
    const float* __restrict__ B = (mode == 0) ? g_k : g_v;
    float* __restrict__ C = (mode == 0) ? g_sp[blockIdx.z] : g_op[blockIdx.z];

    __shared__ float As[32][136];   // [k][m], pad 8 keeps 16B alignment
    __shared__ float Bs[32][64];    // [k][n]

    const int bx = blockIdx.x * 64;               // n offset
    const int by = blockIdx.y * 128;              // m offset
    const int kbase = blockIdx.z * (N / KSPLIT);  // 64-wide K slice
    const int tid = threadIdx.x;
    const int tx = tid & 15;                      // n micro (16*4 = 64)
    const int ty = tid >> 4;                      // m micro (16*8 = 128)

    const int am = tid >> 1;                      // A row 0..127 (2 thr/row)
    const int ah = (tid & 1) * 16;                // A k half offset
    const int bn = (tid & 15) * 4;                // B n, float4
    const int bk = tid >> 4;                      // B k; +16 for 2nd

    float4 aR[4];
#pragma unroll
    for (int j = 0; j < 4; j++)
        aR[j] = *(const float4*)&A[(by + am) * N + kbase + ah + j * 4];
    float4 b0 = *(const float4*)&B[(kbase + bk) * N + bx + bn];
    float4 b1 = *(const float4*)&B[(kbase + bk + 16) * N + bx + bn];

    float acc[8][4] = {};

    for (int k0 = 0; k0 < N / KSPLIT; k0 += 32) {
#pragma unroll
        for (int j = 0; j < 4; j++) {
            As[ah + j * 4 + 0][am] = aR[j].x;
            As[ah + j * 4 + 1][am] = aR[j].y;
            As[ah + j * 4 + 2][am] = aR[j].z;
            As[ah + j * 4 + 3][am] = aR[j].w;
        }
        *(float4*)&Bs[bk][bn]      = b0;
        *(float4*)&Bs[bk + 16][bn] = b1;
        __syncthreads();

        if (k0 + 32 < N / KSPLIT) {
            int kn = kbase + k0 + 32;
#pragma unroll
            for (int j = 0; j < 4; j++)
                aR[j] = *(const float4*)&A[(by + am) * N + kn + ah + j * 4];
            b0 = *(const float4*)&B[(kn + bk) * N + bx + bn];
            b1 = *(const float4*)&B[(kn + bk + 16) * N + bx + bn];
        }

#pragma unroll
        for (int kk = 0; kk < 32; kk++) {
            float4 a0 = *(const float4*)&As[kk][ty * 8];
            float4 a1 = *(const float4*)&As[kk][ty * 8 + 4];
            float4 b  = *(const float4*)&Bs[kk][tx * 4];
            const float* ap0 = (const float*)&a0;
            const float* ap1 = (const float*)&a1;
            const float* bp  = (const float*)&b;
#pragma unroll
            for (int i = 0; i < 4; i++)
#pragma unroll
                for (int j = 0; j < 4; j++) {
                    acc[i][j]     += ap0[i] * bp[j];
                    acc[i + 4][j] += ap1[i] * bp[j];
                }
        }
        __syncthreads();
    }

#pragma unroll
    for (int i = 0; i < 8; i++) {
        float4 r = make_float4(acc[i][0], acc[i][1], acc[i][2], acc[i][3]);
        *(float4*)&C[(by + ty * 8 + i) * N + bx + tx * 4] = r;
    }
}

// ---------------------------------------------------------------------------
// Kernel 3: sum KSPLIT s-partials + row softmax -> g_s.
// 2 rows per block; 128 threads/row; float4 per thread; shuffle reduce.
// ---------------------------------------------------------------------------
__global__ void __launch_bounds__(256) softmax_kernel()
{
    __shared__ float smax[2][4];
    __shared__ float ssum[2][4];

    const int tid = threadIdx.x;
    const int half = tid >> 7;
    const int t = tid & 127;
    const int warp = (tid >> 5) & 3;
    const int lane = tid & 31;
    const int row = blockIdx.x * 2 + half;
    const size_t off = (size_t)row * N + t * 4;

    float4 a = make_float4(0.f, 0.f, 0.f, 0.f);
#pragma unroll
    for (int z = 0; z < KSPLIT; z++) {
        float4 p = *(const float4*)&g_sp[z][off];
        a.x += p.x; a.y += p.y; a.z += p.z; a.w += p.w;
    }

    float mx = fmaxf(fmaxf(a.x, a.y), fmaxf(a.z, a.w));
#pragma unroll
    for (int o = 16; o > 0; o >>= 1)
        mx = fmaxf(mx, __shfl_xor_sync(0xffffffffu, mx, o));
    if (lane == 0) smax[half][warp] = mx;
    __syncthreads();
    mx = fmaxf(fmaxf(smax[half][0], smax[half][1]),
               fmaxf(smax[half][2], smax[half][3]));

    float4 e;
    e.x = __expf(a.x - mx);
    e.y = __expf(a.y - mx);
    e.z = __expf(a.z - mx);
    e.w = __expf(a.w - mx);

    float s = e.x + e.y + e.z + e.w;
#pragma unroll
    for (int o = 16; o > 0; o >>= 1)
        s += __shfl_xor_sync(0xffffffffu, s, o);
    if (lane == 0) ssum[half][warp] = s;
    __syncthreads();
    float inv = 1.0f / (ssum[half][0] + ssum[half][1] + ssum[half][2] + ssum[half][3]);

    e.x *= inv; e.y *= inv; e.z *= inv; e.w *= inv;
    *(float4*)&g_s[off] = e;
}

// ---------------------------------------------------------------------------
// Kernel 5: sum KSPLIT out-partials -> d_out.
// ---------------------------------------------------------------------------
__global__ void __launch_bounds__(256) reduce_out_kernel(float* __restrict__ out)
{
    int i = blockIdx.x * 256 + threadIdx.x;
    float4 r = ((const float4*)g_op[0])[i];
#pragma unroll
    for (int z = 1; z < KSPLIT; z++) {
        float4 s = ((const float4*)g_op[z])[i];
        r.x += s.x; r.y += s.y; r.z += s.z; r.w += s.w;
    }
    ((float4*)out)[i] = r;
}

// ---------------------------------------------------------------------------
extern "C" void kernel_launch(void* const* d_in, const int* in_sizes, int n_in,
                              void* d_out, int out_size)
{
    const float* xq = (const float*)d_in[0];
    const float* xk = (const float*)d_in[1];
    const float* xv = (const float*)d_in[2];
    const float* WQ = (const float*)d_in[3];
    const float* WK = (const float*)d_in[4];
    const float* WV = (const float*)d_in[5];
    float* out = (float*)d_out;

    proj_kernel<<<PROJ_BLOCKS, 256>>>(xq, xk, xv, WQ, WK, WV);

    dim3 gg(N / 64, N / 128, KSPLIT);   // (8, 4, 8) = 256 blocks
    sgemm_kernel<<<gg, 256>>>(0);

    softmax_kernel<<<N / 2, 256>>>();

    sgemm_kernel<<<gg, 256>>>(1);

    reduce_out_kernel<<<(N * N / 4) / 256, 256>>>(out);
}